// round 4
// baseline (speedup 1.0000x reference)
#include <cuda_runtime.h>
#include <math.h>

namespace {
constexpr int B_ = 8, L_ = 256, H_ = 256, NH = 4, D_ = 64, NBLK = 2;
constexpr int ROWS = B_ * L_;          // 2048
constexpr int PLANE = ROWS * H_;       // 524288 = 2^19
}
#define BIGNEG (-4294967295.0f)

// ---- scratch (allocation-free: __device__ globals) ----
__device__ float g_x[PLANE];
__device__ float g_q[PLANE];
__device__ float g_Q[PLANE];
__device__ float g_K[PLANE];
__device__ float g_V[PLANE];
__device__ float g_att[PLANE];
__device__ float g_xa[PLANE];
__device__ float g_h[PLANE];
__device__ float g_P[B_ * NH * L_ * L_];   // 8 MB attention probs
__device__ float g_p0[3 * PLANE];          // split-K partials, slice 0
__device__ float g_p1[3 * PLANE];          // split-K partials, slice 1
__device__ unsigned char g_mask[ROWS];

struct GJobs { const float* A[3]; const float* W[3]; };

// ---- mask dtype sniffer + converter ----
__global__ void k_mask_convert(const void* __restrict__ mraw) {
    __shared__ int s_f32, s_u8;
    const unsigned int* w = (const unsigned int*)mraw;
    int t = threadIdx.x;
    if (t == 0) { s_f32 = 0; s_u8 = 0; }
    __syncthreads();
    for (int i = t; i < 512; i += 256) {
        unsigned int v = w[i];
        if (v == 0x3F800000u) atomicOr(&s_f32, 1);
        if (v & 0xFFFFFF00u)  atomicOr(&s_u8, 1);
    }
    __syncthreads();
    int mode = s_f32 ? 2 : (s_u8 ? 0 : 1);
    const unsigned char* u8 = (const unsigned char*)mraw;
    const int* i32 = (const int*)mraw;
    const float* f32 = (const float*)mraw;
    for (int i = t; i < ROWS; i += 256) {
        unsigned char m;
        if (mode == 0)      m = u8[i] ? 1 : 0;
        else if (mode == 1) m = i32[i] ? 1 : 0;
        else                m = (f32[i] != 0.f) ? 1 : 0;
        g_mask[i] = m;
    }
}

__global__ void k_maskmul(const float* __restrict__ e) {
    int i = blockIdx.x * blockDim.x + threadIdx.x;
    g_x[i] = g_mask[i >> 8] ? 0.f : e[i];
}

// out = LN(in1 (+ in2)) * g + b   (eps=1e-8, biased var)
__global__ void k_ln(const float* __restrict__ in1, const float* __restrict__ in2,
                     const float* __restrict__ gg, const float* __restrict__ bb,
                     float* __restrict__ out) {
    int row = blockIdx.x, t = threadIdx.x;
    float v = in1[row * H_ + t];
    if (in2) v += in2[row * H_ + t];
    __shared__ float r1[8], r2[8];
    __shared__ float mean_s, inv_s;
    float s = v;
    #pragma unroll
    for (int o = 16; o; o >>= 1) s += __shfl_xor_sync(~0u, s, o);
    if ((t & 31) == 0) r1[t >> 5] = s;
    __syncthreads();
    if (t == 0) {
        float tot = 0.f;
        #pragma unroll
        for (int i = 0; i < 8; i++) tot += r1[i];
        mean_s = tot * (1.f / H_);
    }
    __syncthreads();
    float m = mean_s;
    float dv = v - m;
    float sq = dv * dv;
    #pragma unroll
    for (int o = 16; o; o >>= 1) sq += __shfl_xor_sync(~0u, sq, o);
    if ((t & 31) == 0) r2[t >> 5] = sq;
    __syncthreads();
    if (t == 0) {
        float tot = 0.f;
        #pragma unroll
        for (int i = 0; i < 8; i++) tot += r2[i];
        inv_s = rsqrtf(tot * (1.f / H_) + 1e-8f);
    }
    __syncthreads();
    out[row * H_ + t] = dv * inv_s * gg[t] + bb[t];
}

// Batched split-K GEMM: partial[job][i,o] = sum_{d in slice} A[i,d]*W[o,d]
// 64x64 tile, BK=16, 256 threads, 4x4/thread, double-buffered smem.
// grid (N/64, M/64, njobs*2);  z: job = z>>1, slice = z&1 (K half).
__global__ __launch_bounds__(256) void k_gemm_bat(GJobs jobs) {
    __shared__ __align__(16) float As[2][16][64], Ws[2][16][64];
    int job = blockIdx.z >> 1, slice = blockIdx.z & 1;
    const float* A = jobs.A[job];
    const float* W = jobs.W[job];
    float* C = (slice ? g_p1 : g_p0) + job * PLANE;
    int tid = threadIdx.x;
    int tx = tid & 15, ty = tid >> 4;
    int o0 = blockIdx.x * 64, i0 = blockIdx.y * 64;
    int kb = slice * 128;
    int lr = tid >> 2;            // 0..63
    int lc = (tid & 3) * 4;       // 0,4,8,12
    const float* Ap = A + (i0 + lr) * H_ + kb + lc;
    const float* Wp = W + (o0 + lr) * H_ + kb + lc;
    float acc[4][4] = {};
    float4 av = *(const float4*)Ap;
    float4 wv = *(const float4*)Wp;
    As[0][lc + 0][lr] = av.x; As[0][lc + 1][lr] = av.y;
    As[0][lc + 2][lr] = av.z; As[0][lc + 3][lr] = av.w;
    Ws[0][lc + 0][lr] = wv.x; Ws[0][lc + 1][lr] = wv.y;
    Ws[0][lc + 2][lr] = wv.z; Ws[0][lc + 3][lr] = wv.w;
    __syncthreads();
    #pragma unroll
    for (int t = 0; t < 8; t++) {
        int cur = t & 1;
        if (t < 7) {
            av = *(const float4*)(Ap + (t + 1) * 16);
            wv = *(const float4*)(Wp + (t + 1) * 16);
        }
        #pragma unroll
        for (int kk = 0; kk < 16; kk++) {
            float4 a = *(const float4*)&As[cur][kk][ty * 4];
            float4 b = *(const float4*)&Ws[cur][kk][tx * 4];
            acc[0][0] += a.x * b.x; acc[0][1] += a.x * b.y; acc[0][2] += a.x * b.z; acc[0][3] += a.x * b.w;
            acc[1][0] += a.y * b.x; acc[1][1] += a.y * b.y; acc[1][2] += a.y * b.z; acc[1][3] += a.y * b.w;
            acc[2][0] += a.z * b.x; acc[2][1] += a.z * b.y; acc[2][2] += a.z * b.z; acc[2][3] += a.z * b.w;
            acc[3][0] += a.w * b.x; acc[3][1] += a.w * b.y; acc[3][2] += a.w * b.z; acc[3][3] += a.w * b.w;
        }
        if (t < 7) {
            int nb = 1 - cur;
            As[nb][lc + 0][lr] = av.x; As[nb][lc + 1][lr] = av.y;
            As[nb][lc + 2][lr] = av.z; As[nb][lc + 3][lr] = av.w;
            Ws[nb][lc + 0][lr] = wv.x; Ws[nb][lc + 1][lr] = wv.y;
            Ws[nb][lc + 2][lr] = wv.z; Ws[nb][lc + 3][lr] = wv.w;
            __syncthreads();
        }
    }
    #pragma unroll
    for (int i = 0; i < 4; i++) {
        int row = i0 + ty * 4 + i, o = o0 + tx * 4;
        *(float4*)(C + row * H_ + o) =
            make_float4(acc[i][0], acc[i][1], acc[i][2], acc[i][3]);
    }
}

// combine QKV partials: Q += bq ; K += bk+posK ; V += bv+posV
__global__ void k_epi_qkv(const float* __restrict__ bq, const float* __restrict__ bk,
                          const float* __restrict__ bv, const float* __restrict__ posK,
                          const float* __restrict__ posV) {
    int idx = blockIdx.x * blockDim.x + threadIdx.x;   // 0 .. 3*PLANE
    int s = idx >> 19;
    int e = idx & (PLANE - 1);
    int o = e & 255;
    int kpos = (e >> 8) & 255;
    float v = g_p0[idx] + g_p1[idx];
    if (s == 0)      g_Q[e] = v + bq[o];
    else if (s == 1) g_K[e] = v + bk[o] + posK[(kpos << 8) | o];
    else             g_V[e] = v + bv[o] + posV[(kpos << 8) | o];
}

// h = relu(p0+p1+b1)
__global__ void k_epi_relu(const float* __restrict__ b1) {
    int e = blockIdx.x * blockDim.x + threadIdx.x;
    g_h[e] = fmaxf(g_p0[e] + g_p1[e] + b1[e & 255], 0.f);
}

// x = (p0+p1+b2+res) * keep
__global__ void k_epi_res(const float* __restrict__ b2, const float* __restrict__ res) {
    int e = blockIdx.x * blockDim.x + threadIdx.x;
    float v = g_p0[e] + g_p1[e] + b2[e & 255] + res[e];
    g_x[e] = g_mask[e >> 8] ? 0.f : v;
}

// scores + softmax -> g_P.  block per (b, 4-query tile); 16 warps: warp = (qi,head).
__global__ __launch_bounds__(512) void k_attn_score(const int* __restrict__ tm,
                                                    const float* __restrict__ tK) {
    int blk = blockIdx.x;                 // 0..511
    int b = blk >> 6, q0 = (blk & 63) * 4;
    int w = threadIdx.x >> 5, lane = threadIdx.x & 31;
    int h = w & 3, qi = w >> 2;
    int q = q0 + qi;
    int bq = (b << 8) | q;
    __shared__ float Qs[4][H_];           // 4 KB
    __shared__ float S[16][L_];           // 16 KB
    for (int i = threadIdx.x; i < 4 * H_; i += 512)
        Qs[i >> 8][i & 255] = g_Q[((b << 8) | (q0 + (i >> 8))) * H_ + (i & 255)];
    for (int k = lane; k < L_; k += 32) S[w][k] = BIGNEG;
    __syncthreads();
    int hd = h * D_;
    float q0r = Qs[qi][hd + lane], q1r = Qs[qi][hd + lane + 32];
    if (!g_mask[bq]) {
        const int* tmr = tm + (long)bq * L_;
        for (int k = 0; k <= q; k++) {
            int t = tmr[k];
            const float* Kr = g_K + ((b << 8) | k) * H_ + hd;
            const float* tr = tK + t * H_ + hd;
            float s = q0r * (Kr[lane] + tr[lane]);
            int d2 = lane + 32;
            s += q1r * (Kr[d2] + tr[d2]);
            #pragma unroll
            for (int o = 16; o; o >>= 1) s += __shfl_xor_sync(~0u, s, o);
            if (lane == 0) S[w][k] = s * 0.125f;
        }
    }
    __syncwarp();
    float e[8];
    float mx = BIGNEG;
    #pragma unroll
    for (int j = 0; j < 8; j++) { e[j] = S[w][lane + 32 * j]; mx = fmaxf(mx, e[j]); }
    #pragma unroll
    for (int o = 16; o; o >>= 1) mx = fmaxf(mx, __shfl_xor_sync(~0u, mx, o));
    float sum = 0.f;
    #pragma unroll
    for (int j = 0; j < 8; j++) { e[j] = __expf(e[j] - mx); sum += e[j]; }
    #pragma unroll
    for (int o = 16; o; o >>= 1) sum += __shfl_xor_sync(~0u, sum, o);
    float inv = 1.f / sum;
    float* Pr = g_P + (((long)(b * NH + h) * L_ + q) * L_);
    #pragma unroll
    for (int j = 0; j < 8; j++) Pr[lane + 32 * j] = e[j] * inv;
}

// out[b,q,:] = sum_k p*(V'+tV).  block per (b, 4-query tile); 1024 thr = (qi, d).
__global__ __launch_bounds__(1024) void k_attn_out(const int* __restrict__ tm,
                                                   const float* __restrict__ tV) {
    int blk = blockIdx.x;
    int b = blk >> 6, q0 = (blk & 63) * 4;
    int qi = threadIdx.x >> 8, d = threadIdx.x & 255, h = d >> 6;
    int q = q0 + qi;
    int bq = (b << 8) | q;
    __shared__ float ps[4][NH][L_];       // 16 KB
    __shared__ int ts[4][L_];             // 4 KB
    #pragma unroll
    for (int j = 0; j < NH; j++)
        ps[qi][j][d] = g_P[(((long)(b * NH + j) * L_ + q) * L_) + d];
    ts[qi][d] = tm[(long)bq * L_ + d];
    __syncthreads();
    int kmax = g_mask[bq] ? (L_ - 1) : q;
    float acc = 0.f;
    for (int k = 0; k <= kmax; k++) {
        float p = ps[qi][h][k];
        acc += p * (g_V[((b << 8) | k) * H_ + d] + tV[ts[qi][k] * H_ + d]);
    }
    g_att[bq * H_ + d] = acc;
}

extern "C" void kernel_launch(void* const* d_in, const int* in_sizes, int n_in,
                              void* d_out, int out_size) {
    const void*  mraw = d_in[0];
    const float* seq  = (const float*)d_in[1];
    const int*   tm   = (const int*)d_in[3];
    int base = (n_in >= 25 && in_sizes[4] == 1) ? 5 : 4;
    const float* Wq   = (const float*)d_in[base + 0];  const float* bq  = (const float*)d_in[base + 1];
    const float* Wk   = (const float*)d_in[base + 2];  const float* bk  = (const float*)d_in[base + 3];
    const float* Wv   = (const float*)d_in[base + 4];  const float* bv  = (const float*)d_in[base + 5];
    const float* ln1g = (const float*)d_in[base + 6];  const float* ln1b = (const float*)d_in[base + 7];
    const float* ln2g = (const float*)d_in[base + 8];  const float* ln2b = (const float*)d_in[base + 9];
    const float* W1   = (const float*)d_in[base + 10]; const float* b1  = (const float*)d_in[base + 11];
    const float* W2   = (const float*)d_in[base + 12]; const float* b2  = (const float*)d_in[base + 13];
    const float* posK = (const float*)d_in[base + 14]; const float* posV = (const float*)d_in[base + 15];
    const float* tK   = (const float*)d_in[base + 16]; const float* tV  = (const float*)d_in[base + 17];
    const float* lnfg = (const float*)d_in[base + 18]; const float* lnfb = (const float*)d_in[base + 19];
    float* out = (float*)d_out;

    float *px, *pq, *patt, *pxa, *ph;
    cudaGetSymbolAddress((void**)&px,  g_x);
    cudaGetSymbolAddress((void**)&pq,  g_q);
    cudaGetSymbolAddress((void**)&patt, g_att);
    cudaGetSymbolAddress((void**)&pxa, g_xa);
    cudaGetSymbolAddress((void**)&ph,  g_h);

    k_mask_convert<<<1, 256>>>(mraw);
    k_maskmul<<<PLANE / 256, 256>>>(seq);
    for (int i = 0; i < NBLK; i++) {
        const float* wq = Wq + (long)i * H_ * H_;
        const float* wk = Wk + (long)i * H_ * H_;
        const float* wv = Wv + (long)i * H_ * H_;
        const float* w1 = W1 + (long)i * H_ * H_;
        const float* w2 = W2 + (long)i * H_ * H_;

        k_ln<<<ROWS, 256>>>(px, nullptr, ln1g + i * H_, ln1b + i * H_, pq);

        GJobs jq; jq.A[0] = pq; jq.W[0] = wq; jq.A[1] = px; jq.W[1] = wk;
        jq.A[2] = px; jq.W[2] = wv;
        k_gemm_bat<<<dim3(4, 32, 6), 256>>>(jq);
        k_epi_qkv<<<3 * PLANE / 256, 256>>>(bq + i * H_, bk + i * H_, bv + i * H_,
                                            posK, posV);

        k_attn_score<<<512, 512>>>(tm, tK);
        k_attn_out<<<512, 1024>>>(tm, tV);

        k_ln<<<ROWS, 256>>>(pq, patt, ln2g + i * H_, ln2b + i * H_, pxa);

        GJobs j1; j1.A[0] = pxa; j1.W[0] = w1; j1.A[1] = nullptr; j1.W[1] = nullptr;
        j1.A[2] = nullptr; j1.W[2] = nullptr;
        k_gemm_bat<<<dim3(4, 32, 2), 256>>>(j1);
        k_epi_relu<<<PLANE / 256, 256>>>(b1 + i * H_);

        GJobs j2; j2.A[0] = ph; j2.W[0] = w2; j2.A[1] = nullptr; j2.W[1] = nullptr;
        j2.A[2] = nullptr; j2.W[2] = nullptr;
        k_gemm_bat<<<dim3(4, 32, 2), 256>>>(j2);
        k_epi_res<<<PLANE / 256, 256>>>(b2 + i * H_, pxa);
    }
    k_ln<<<ROWS, 256>>>(px, nullptr, lnfg, lnfb, out);
}

// round 5
// speedup vs baseline: 1.1555x; 1.1555x over previous
#include <cuda_runtime.h>
#include <math.h>

namespace {
constexpr int B_ = 8, L_ = 256, H_ = 256, NH = 4, D_ = 64, NBLK = 2;
constexpr int ROWS = B_ * L_;          // 2048
constexpr int PLANE = ROWS * H_;       // 524288 = 2^19
}
#define BIGNEG (-4294967295.0f)

// ---- scratch (allocation-free: __device__ globals) ----
__device__ float g_x[PLANE];
__device__ float g_q[PLANE];
__device__ float g_Q[PLANE];
__device__ float g_K[PLANE];
__device__ float g_V[PLANE];
__device__ float g_att[PLANE];
__device__ float g_xa[PLANE];
__device__ float g_h[PLANE];
__device__ float g_p0[3 * PLANE];          // split-K partials, slice 0
__device__ float g_p1[3 * PLANE];          // split-K partials, slice 1
__device__ unsigned char g_mask[ROWS];

struct GJobs { const float* A[3]; const float* W[3]; };

// ---- mask dtype sniffer + converter ----
__global__ void k_mask_convert(const void* __restrict__ mraw) {
    __shared__ int s_f32, s_u8;
    const unsigned int* w = (const unsigned int*)mraw;
    int t = threadIdx.x;
    if (t == 0) { s_f32 = 0; s_u8 = 0; }
    __syncthreads();
    for (int i = t; i < 512; i += 256) {
        unsigned int v = w[i];
        if (v == 0x3F800000u) atomicOr(&s_f32, 1);
        if (v & 0xFFFFFF00u)  atomicOr(&s_u8, 1);
    }
    __syncthreads();
    int mode = s_f32 ? 2 : (s_u8 ? 0 : 1);
    const unsigned char* u8 = (const unsigned char*)mraw;
    const int* i32 = (const int*)mraw;
    const float* f32 = (const float*)mraw;
    for (int i = t; i < ROWS; i += 256) {
        unsigned char m;
        if (mode == 0)      m = u8[i] ? 1 : 0;
        else if (mode == 1) m = i32[i] ? 1 : 0;
        else                m = (f32[i] != 0.f) ? 1 : 0;
        g_mask[i] = m;
    }
}

__global__ void k_maskmul(const float* __restrict__ e) {
    int i = blockIdx.x * blockDim.x + threadIdx.x;
    g_x[i] = g_mask[i >> 8] ? 0.f : e[i];
}

// out = LN(in1 (+ in2)) * g + b   (eps=1e-8, biased var)
__global__ void k_ln(const float* __restrict__ in1, const float* __restrict__ in2,
                     const float* __restrict__ gg, const float* __restrict__ bb,
                     float* __restrict__ out) {
    int row = blockIdx.x, t = threadIdx.x;
    float v = in1[row * H_ + t];
    if (in2) v += in2[row * H_ + t];
    __shared__ float r1[8], r2[8];
    __shared__ float mean_s, inv_s;
    float s = v;
    #pragma unroll
    for (int o = 16; o; o >>= 1) s += __shfl_xor_sync(~0u, s, o);
    if ((t & 31) == 0) r1[t >> 5] = s;
    __syncthreads();
    if (t == 0) {
        float tot = 0.f;
        #pragma unroll
        for (int i = 0; i < 8; i++) tot += r1[i];
        mean_s = tot * (1.f / H_);
    }
    __syncthreads();
    float m = mean_s;
    float dv = v - m;
    float sq = dv * dv;
    #pragma unroll
    for (int o = 16; o; o >>= 1) sq += __shfl_xor_sync(~0u, sq, o);
    if ((t & 31) == 0) r2[t >> 5] = sq;
    __syncthreads();
    if (t == 0) {
        float tot = 0.f;
        #pragma unroll
        for (int i = 0; i < 8; i++) tot += r2[i];
        inv_s = rsqrtf(tot * (1.f / H_) + 1e-8f);
    }
    __syncthreads();
    out[row * H_ + t] = dv * inv_s * gg[t] + bb[t];
}

// Batched split-K GEMM (as R4): 64x64 tile, BK=16, 256 thr, 4x4/thread, dbuf.
__global__ __launch_bounds__(256) void k_gemm_bat(GJobs jobs) {
    __shared__ __align__(16) float As[2][16][64], Ws[2][16][64];
    int job = blockIdx.z >> 1, slice = blockIdx.z & 1;
    const float* A = jobs.A[job];
    const float* W = jobs.W[job];
    float* C = (slice ? g_p1 : g_p0) + job * PLANE;
    int tid = threadIdx.x;
    int tx = tid & 15, ty = tid >> 4;
    int o0 = blockIdx.x * 64, i0 = blockIdx.y * 64;
    int kb = slice * 128;
    int lr = tid >> 2;
    int lc = (tid & 3) * 4;
    const float* Ap = A + (i0 + lr) * H_ + kb + lc;
    const float* Wp = W + (o0 + lr) * H_ + kb + lc;
    float acc[4][4] = {};
    float4 av = *(const float4*)Ap;
    float4 wv = *(const float4*)Wp;
    As[0][lc + 0][lr] = av.x; As[0][lc + 1][lr] = av.y;
    As[0][lc + 2][lr] = av.z; As[0][lc + 3][lr] = av.w;
    Ws[0][lc + 0][lr] = wv.x; Ws[0][lc + 1][lr] = wv.y;
    Ws[0][lc + 2][lr] = wv.z; Ws[0][lc + 3][lr] = wv.w;
    __syncthreads();
    #pragma unroll
    for (int t = 0; t < 8; t++) {
        int cur = t & 1;
        if (t < 7) {
            av = *(const float4*)(Ap + (t + 1) * 16);
            wv = *(const float4*)(Wp + (t + 1) * 16);
        }
        #pragma unroll
        for (int kk = 0; kk < 16; kk++) {
            float4 a = *(const float4*)&As[cur][kk][ty * 4];
            float4 b = *(const float4*)&Ws[cur][kk][tx * 4];
            acc[0][0] += a.x * b.x; acc[0][1] += a.x * b.y; acc[0][2] += a.x * b.z; acc[0][3] += a.x * b.w;
            acc[1][0] += a.y * b.x; acc[1][1] += a.y * b.y; acc[1][2] += a.y * b.z; acc[1][3] += a.y * b.w;
            acc[2][0] += a.z * b.x; acc[2][1] += a.z * b.y; acc[2][2] += a.z * b.z; acc[2][3] += a.z * b.w;
            acc[3][0] += a.w * b.x; acc[3][1] += a.w * b.y; acc[3][2] += a.w * b.z; acc[3][3] += a.w * b.w;
        }
        if (t < 7) {
            int nb = 1 - cur;
            As[nb][lc + 0][lr] = av.x; As[nb][lc + 1][lr] = av.y;
            As[nb][lc + 2][lr] = av.z; As[nb][lc + 3][lr] = av.w;
            Ws[nb][lc + 0][lr] = wv.x; Ws[nb][lc + 1][lr] = wv.y;
            Ws[nb][lc + 2][lr] = wv.z; Ws[nb][lc + 3][lr] = wv.w;
            __syncthreads();
        }
    }
    #pragma unroll
    for (int i = 0; i < 4; i++) {
        int row = i0 + ty * 4 + i, o = o0 + tx * 4;
        *(float4*)(C + row * H_ + o) =
            make_float4(acc[i][0], acc[i][1], acc[i][2], acc[i][3]);
    }
}

// combine QKV partials: Q += bq ; K += bk+posK ; V += bv+posV
__global__ void k_epi_qkv(const float* __restrict__ bq, const float* __restrict__ bk,
                          const float* __restrict__ bv, const float* __restrict__ posK,
                          const float* __restrict__ posV) {
    int idx = blockIdx.x * blockDim.x + threadIdx.x;
    int s = idx >> 19;
    int e = idx & (PLANE - 1);
    int o = e & 255;
    int kpos = (e >> 8) & 255;
    float v = g_p0[idx] + g_p1[idx];
    if (s == 0)      g_Q[e] = v + bq[o];
    else if (s == 1) g_K[e] = v + bk[o] + posK[(kpos << 8) | o];
    else             g_V[e] = v + bv[o] + posV[(kpos << 8) | o];
}

__global__ void k_epi_relu(const float* __restrict__ b1) {
    int e = blockIdx.x * blockDim.x + threadIdx.x;
    g_h[e] = fmaxf(g_p0[e] + g_p1[e] + b1[e & 255], 0.f);
}

__global__ void k_epi_res(const float* __restrict__ b2, const float* __restrict__ res) {
    int e = blockIdx.x * blockDim.x + threadIdx.x;
    float v = g_p0[e] + g_p1[e] + b2[e & 255] + res[e];
    g_x[e] = g_mask[e >> 8] ? 0.f : v;
}

// Fused attention: scores + softmax + output, one block per (b, qt).
// Queries {qt, 127-qt, 128+qt, 255-qt} -> constant work per block.
__global__ __launch_bounds__(512) void k_attn(const int* __restrict__ tm,
                                              const float* __restrict__ tK,
                                              const float* __restrict__ tV) {
    int blk = blockIdx.x;                  // 0..511
    int b = blk >> 6, qt = blk & 63;
    int tid = threadIdx.x;
    __shared__ float Qs[4][H_];            // 4 KB
    __shared__ float S[16][L_];            // 16 KB (scores, then probs)
    __shared__ int ts[4][L_];              // 4 KB
    __shared__ int qs_s[4];

    if (tid < 4) {
        int j = tid;
        int q = (j == 0) ? qt : (j == 1) ? (127 - qt) : (j == 2) ? (128 + qt) : (255 - qt);
        qs_s[j] = q;
    }
    __syncthreads();
    // stage Q rows and time indices
    for (int i = tid; i < 4 * H_; i += 512) {
        int qi = i >> 8, c = i & 255;
        Qs[qi][c] = g_Q[(((b << 8) | qs_s[qi]) << 8) + c];
        ts[qi][c] = tm[(long)(((b << 8) | qs_s[qi])) * L_ + c];
    }
    for (int i = tid; i < 16 * L_; i += 512)
        S[i >> 8][i & 255] = BIGNEG;
    __syncthreads();

    // ---- phase 1: scores ----
    int w = tid >> 5, lane = tid & 31;
    int qi = w >> 2, h = w & 3;
    int q = qs_s[qi];
    int bq = (b << 8) | q;
    int hd = h * D_;
    float q0r = Qs[qi][hd + lane], q1r = Qs[qi][hd + lane + 32];
    if (!g_mask[bq]) {
        for (int k = 0; k <= q; k++) {
            int t = ts[qi][k];
            const float* Kr = g_K + (((b << 8) | k) << 8) + hd;
            const float* tr = tK + (t << 8) + hd;
            float s = q0r * (Kr[lane] + tr[lane]);
            int d2 = lane + 32;
            s += q1r * (Kr[d2] + tr[d2]);
            #pragma unroll
            for (int o = 16; o; o >>= 1) s += __shfl_xor_sync(~0u, s, o);
            if (lane == 0) S[w][k] = s * 0.125f;
        }
    }
    __syncwarp();
    // ---- phase 2: softmax (per warp) ----
    float e[8];
    float mx = BIGNEG;
    #pragma unroll
    for (int j = 0; j < 8; j++) { e[j] = S[w][lane + 32 * j]; mx = fmaxf(mx, e[j]); }
    #pragma unroll
    for (int o = 16; o; o >>= 1) mx = fmaxf(mx, __shfl_xor_sync(~0u, mx, o));
    float sum = 0.f;
    #pragma unroll
    for (int j = 0; j < 8; j++) { e[j] = __expf(e[j] - mx); sum += e[j]; }
    #pragma unroll
    for (int o = 16; o; o >>= 1) sum += __shfl_xor_sync(~0u, sum, o);
    float inv = 1.f / sum;
    #pragma unroll
    for (int j = 0; j < 8; j++) S[w][lane + 32 * j] = e[j] * inv;
    __syncthreads();

    // ---- phase 3: output ----  thread = (qi2, d-pair)
    int qi2 = tid >> 7, dp = (tid & 127) * 2;
    int h2 = dp >> 6;
    int q2 = qs_s[qi2];
    int bq2 = (b << 8) | q2;
    int kmax = g_mask[bq2] ? (L_ - 1) : q2;
    const float* Sp = S[qi2 * 4 + h2];
    float a0 = 0.f, a1 = 0.f;
    for (int k = 0; k <= kmax; k++) {
        float p = Sp[k];
        float2 v = *(const float2*)(g_V + (((b << 8) | k) << 8) + dp);
        float2 tv = *(const float2*)(tV + (ts[qi2][k] << 8) + dp);
        a0 += p * (v.x + tv.x);
        a1 += p * (v.y + tv.y);
    }
    g_att[(bq2 << 8) + dp] = a0;
    g_att[(bq2 << 8) + dp + 1] = a1;
}

extern "C" void kernel_launch(void* const* d_in, const int* in_sizes, int n_in,
                              void* d_out, int out_size) {
    const void*  mraw = d_in[0];
    const float* seq  = (const float*)d_in[1];
    const int*   tm   = (const int*)d_in[3];
    int base = (n_in >= 25 && in_sizes[4] == 1) ? 5 : 4;
    const float* Wq   = (const float*)d_in[base + 0];  const float* bq  = (const float*)d_in[base + 1];
    const float* Wk   = (const float*)d_in[base + 2];  const float* bk  = (const float*)d_in[base + 3];
    const float* Wv   = (const float*)d_in[base + 4];  const float* bv  = (const float*)d_in[base + 5];
    const float* ln1g = (const float*)d_in[base + 6];  const float* ln1b = (const float*)d_in[base + 7];
    const float* ln2g = (const float*)d_in[base + 8];  const float* ln2b = (const float*)d_in[base + 9];
    const float* W1   = (const float*)d_in[base + 10]; const float* b1  = (const float*)d_in[base + 11];
    const float* W2   = (const float*)d_in[base + 12]; const float* b2  = (const float*)d_in[base + 13];
    const float* posK = (const float*)d_in[base + 14]; const float* posV = (const float*)d_in[base + 15];
    const float* tK   = (const float*)d_in[base + 16]; const float* tV  = (const float*)d_in[base + 17];
    const float* lnfg = (const float*)d_in[base + 18]; const float* lnfb = (const float*)d_in[base + 19];
    float* out = (float*)d_out;

    float *px, *pq, *patt, *pxa, *ph;
    cudaGetSymbolAddress((void**)&px,  g_x);
    cudaGetSymbolAddress((void**)&pq,  g_q);
    cudaGetSymbolAddress((void**)&patt, g_att);
    cudaGetSymbolAddress((void**)&pxa, g_xa);
    cudaGetSymbolAddress((void**)&ph,  g_h);

    k_mask_convert<<<1, 256>>>(mraw);
    k_maskmul<<<PLANE / 256, 256>>>(seq);
    for (int i = 0; i < NBLK; i++) {
        const float* wq = Wq + (long)i * H_ * H_;
        const float* wk = Wk + (long)i * H_ * H_;
        const float* wv = Wv + (long)i * H_ * H_;
        const float* w1 = W1 + (long)i * H_ * H_;
        const float* w2 = W2 + (long)i * H_ * H_;

        k_ln<<<ROWS, 256>>>(px, nullptr, ln1g + i * H_, ln1b + i * H_, pq);

        GJobs jq; jq.A[0] = pq; jq.W[0] = wq; jq.A[1] = px; jq.W[1] = wk;
        jq.A[2] = px; jq.W[2] = wv;
        k_gemm_bat<<<dim3(4, 32, 6), 256>>>(jq);
        k_epi_qkv<<<3 * PLANE / 256, 256>>>(bq + i * H_, bk + i * H_, bv + i * H_,
                                            posK, posV);

        k_attn<<<512, 512>>>(tm, tK, tV);

        k_ln<<<ROWS, 256>>>(pq, patt, ln2g + i * H_, ln2b + i * H_, pxa);

        GJobs j1; j1.A[0] = pxa; j1.W[0] = w1; j1.A[1] = nullptr; j1.W[1] = nullptr;
        j1.A[2] = nullptr; j1.W[2] = nullptr;
        k_gemm_bat<<<dim3(4, 32, 2), 256>>>(j1);
        k_epi_relu<<<PLANE / 256, 256>>>(b1 + i * H_);

        GJobs j2; j2.A[0] = ph; j2.W[0] = w2; j2.A[1] = nullptr; j2.W[1] = nullptr;
        j2.A[2] = nullptr; j2.W[2] = nullptr;
        k_gemm_bat<<<dim3(4, 32, 2), 256>>>(j2);
        k_epi_res<<<PLANE / 256, 256>>>(b2 + i * H_, pxa);
    }
    k_ln<<<ROWS, 256>>>(px, nullptr, lnfg, lnfb, out);
}

// round 6
// speedup vs baseline: 1.1569x; 1.0012x over previous
#include <cuda_runtime.h>
#include <math.h>

namespace {
constexpr int B_ = 8, L_ = 256, H_ = 256, NH = 4, D_ = 64, NBLK = 2;
constexpr int ROWS = B_ * L_;          // 2048
constexpr int PLANE = ROWS * H_;       // 524288 = 2^19
}
#define BIGNEG (-4294967295.0f)

// ---- scratch (allocation-free: __device__ globals) ----
__device__ float g_x[PLANE];
__device__ float g_q[PLANE];
__device__ float g_Q[PLANE];
__device__ float g_K[PLANE];
__device__ float g_V[PLANE];
__device__ float g_att[PLANE];
__device__ float g_xa[PLANE];
__device__ float g_h[PLANE];
__device__ unsigned char g_mask[ROWS];

// job: C = epilogue(A @ W^T)
// mode 0: +bias            -> C
// mode 1: +bias+posK       -> C
// mode 2: +bias+posV       -> C
// mode 3: relu(+bias)      -> C
// mode 4: (+bias+aux)*keep -> C   (aux = residual)
struct TJob { const float* A; const float* W; const float* bias;
              const float* aux; float* C; int mode; };
struct TJobs { TJob j[3]; };

// ---- mask dtype sniffer + converter ----
__global__ void k_mask_convert(const void* __restrict__ mraw) {
    __shared__ int s_f32, s_u8;
    const unsigned int* w = (const unsigned int*)mraw;
    int t = threadIdx.x;
    if (t == 0) { s_f32 = 0; s_u8 = 0; }
    __syncthreads();
    for (int i = t; i < 512; i += 256) {
        unsigned int v = w[i];
        if (v == 0x3F800000u) atomicOr(&s_f32, 1);
        if (v & 0xFFFFFF00u)  atomicOr(&s_u8, 1);
    }
    __syncthreads();
    int mode = s_f32 ? 2 : (s_u8 ? 0 : 1);
    const unsigned char* u8 = (const unsigned char*)mraw;
    const int* i32 = (const int*)mraw;
    const float* f32 = (const float*)mraw;
    for (int i = t; i < ROWS; i += 256) {
        unsigned char m;
        if (mode == 0)      m = u8[i] ? 1 : 0;
        else if (mode == 1) m = i32[i] ? 1 : 0;
        else                m = (f32[i] != 0.f) ? 1 : 0;
        g_mask[i] = m;
    }
}

__global__ void k_maskmul(const float* __restrict__ e) {
    int i = blockIdx.x * blockDim.x + threadIdx.x;
    g_x[i] = g_mask[i >> 8] ? 0.f : e[i];
}

// out = LN(in1 (+ in2)) * g + b   (eps=1e-8, biased var)
__global__ void k_ln(const float* __restrict__ in1, const float* __restrict__ in2,
                     const float* __restrict__ gg, const float* __restrict__ bb,
                     float* __restrict__ out) {
    int row = blockIdx.x, t = threadIdx.x;
    float v = in1[row * H_ + t];
    if (in2) v += in2[row * H_ + t];
    __shared__ float r1[8], r2[8];
    __shared__ float mean_s, inv_s;
    float s = v;
    #pragma unroll
    for (int o = 16; o; o >>= 1) s += __shfl_xor_sync(~0u, s, o);
    if ((t & 31) == 0) r1[t >> 5] = s;
    __syncthreads();
    if (t == 0) {
        float tot = 0.f;
        #pragma unroll
        for (int i = 0; i < 8; i++) tot += r1[i];
        mean_s = tot * (1.f / H_);
    }
    __syncthreads();
    float m = mean_s;
    float dv = v - m;
    float sq = dv * dv;
    #pragma unroll
    for (int o = 16; o; o >>= 1) sq += __shfl_xor_sync(~0u, sq, o);
    if ((t & 31) == 0) r2[t >> 5] = sq;
    __syncthreads();
    if (t == 0) {
        float tot = 0.f;
        #pragma unroll
        for (int i = 0; i < 8; i++) tot += r2[i];
        inv_s = rsqrtf(tot * (1.f / H_) + 1e-8f);
    }
    __syncthreads();
    out[row * H_ + t] = dv * inv_s * gg[t] + bb[t];
}

// ---- tf32 mma helpers ----
__device__ __forceinline__ unsigned f2tf(float f) {
    unsigned u;
    asm("cvt.rna.tf32.f32 %0, %1;" : "=r"(u) : "f"(f));
    return u;
}
__device__ __forceinline__ void mma8(float* d, unsigned a0, unsigned a1,
                                     unsigned a2, unsigned a3,
                                     unsigned b0, unsigned b1) {
    asm volatile(
        "mma.sync.aligned.m16n8k8.row.col.f32.tf32.tf32.f32 "
        "{%0,%1,%2,%3}, {%4,%5,%6,%7}, {%8,%9}, {%0,%1,%2,%3};"
        : "+f"(d[0]), "+f"(d[1]), "+f"(d[2]), "+f"(d[3])
        : "r"(a0), "r"(a1), "r"(a2), "r"(a3), "r"(b0), "r"(b1));
}

// Tensor-core GEMM with split-tf32 (fp32 accuracy): C = A[2048,256] @ W[256,256]^T.
// 64x64 tile, BK=32, 256 threads (8 warps, warp = 16x32), fused epilogue.
__global__ __launch_bounds__(256) void k_gemm_tc(TJobs jobs) {
    const TJob J = jobs.j[blockIdx.z];
    __shared__ unsigned As_h[64][36], As_l[64][36];
    __shared__ unsigned Ws_h[64][36], Ws_l[64][36];
    int tid = threadIdx.x;
    int w = tid >> 5, lane = tid & 31;
    int wm = w & 3, wn = w >> 2;
    int o0 = blockIdx.x * 64, i0 = blockIdx.y * 64;
    int g = lane >> 2, t4 = lane & 3;

    int sr = tid >> 2;               // staging row 0..63
    int sc = (tid & 3) * 8;          // staging col group
    const float* Ap = J.A + (i0 + sr) * H_ + sc;
    const float* Wp = J.W + (o0 + sr) * H_ + sc;

    float acc[4][4] = {};
    float4 av0 = *(const float4*)Ap,        av1 = *(const float4*)(Ap + 4);
    float4 wv0 = *(const float4*)Wp,        wv1 = *(const float4*)(Wp + 4);

    #pragma unroll
    for (int tile = 0; tile < 8; tile++) {
        // split+stage current tile
        float abuf[8] = {av0.x, av0.y, av0.z, av0.w, av1.x, av1.y, av1.z, av1.w};
        float wbuf[8] = {wv0.x, wv0.y, wv0.z, wv0.w, wv1.x, wv1.y, wv1.z, wv1.w};
        #pragma unroll
        for (int j = 0; j < 8; j++) {
            unsigned h = f2tf(abuf[j]);
            As_h[sr][sc + j] = h;
            As_l[sr][sc + j] = f2tf(abuf[j] - __uint_as_float(h));
            unsigned hw = f2tf(wbuf[j]);
            Ws_h[sr][sc + j] = hw;
            Ws_l[sr][sc + j] = f2tf(wbuf[j] - __uint_as_float(hw));
        }
        __syncthreads();
        if (tile < 7) {
            av0 = *(const float4*)(Ap + (tile + 1) * 32);
            av1 = *(const float4*)(Ap + (tile + 1) * 32 + 4);
            wv0 = *(const float4*)(Wp + (tile + 1) * 32);
            wv1 = *(const float4*)(Wp + (tile + 1) * 32 + 4);
        }
        #pragma unroll
        for (int kk = 0; kk < 32; kk += 8) {
            int ar0 = wm * 16 + g, ar1 = ar0 + 8;
            unsigned ah0 = As_h[ar0][kk + t4],     ah1 = As_h[ar1][kk + t4];
            unsigned ah2 = As_h[ar0][kk + t4 + 4], ah3 = As_h[ar1][kk + t4 + 4];
            unsigned al0 = As_l[ar0][kk + t4],     al1 = As_l[ar1][kk + t4];
            unsigned al2 = As_l[ar0][kk + t4 + 4], al3 = As_l[ar1][kk + t4 + 4];
            #pragma unroll
            for (int nf = 0; nf < 4; nf++) {
                int nb = wn * 32 + nf * 8 + g;
                unsigned bh0 = Ws_h[nb][kk + t4], bh1 = Ws_h[nb][kk + t4 + 4];
                unsigned bl0 = Ws_l[nb][kk + t4], bl1 = Ws_l[nb][kk + t4 + 4];
                mma8(acc[nf], ah0, ah1, ah2, ah3, bh0, bh1);
                mma8(acc[nf], al0, al1, al2, al3, bh0, bh1);
                mma8(acc[nf], ah0, ah1, ah2, ah3, bl0, bl1);
            }
        }
        __syncthreads();
    }

    // fused epilogue
    int mode = J.mode;
    int row0 = i0 + wm * 16 + g, row1 = row0 + 8;
    #pragma unroll
    for (int nf = 0; nf < 4; nf++) {
        int col = o0 + wn * 32 + nf * 8 + 2 * t4;
        float b0 = J.bias[col], b1 = J.bias[col + 1];
        float v00 = acc[nf][0] + b0, v01 = acc[nf][1] + b1;
        float v10 = acc[nf][2] + b0, v11 = acc[nf][3] + b1;
        if (mode == 1 || mode == 2) {
            const float* pos = J.aux;
            v00 += pos[((row0 & 255) << 8) | col];
            v01 += pos[((row0 & 255) << 8) | (col + 1)];
            v10 += pos[((row1 & 255) << 8) | col];
            v11 += pos[((row1 & 255) << 8) | (col + 1)];
        } else if (mode == 3) {
            v00 = fmaxf(v00, 0.f); v01 = fmaxf(v01, 0.f);
            v10 = fmaxf(v10, 0.f); v11 = fmaxf(v11, 0.f);
        } else if (mode == 4) {
            v00 += J.aux[row0 * H_ + col]; v01 += J.aux[row0 * H_ + col + 1];
            v10 += J.aux[row1 * H_ + col]; v11 += J.aux[row1 * H_ + col + 1];
            if (g_mask[row0]) { v00 = 0.f; v01 = 0.f; }
            if (g_mask[row1]) { v10 = 0.f; v11 = 0.f; }
        }
        *(float2*)(J.C + row0 * H_ + col) = make_float2(v00, v01);
        *(float2*)(J.C + row1 * H_ + col) = make_float2(v10, v11);
    }
}

// Fused attention (as R5): one block per (b, qt), balanced queries.
__global__ __launch_bounds__(512) void k_attn(const int* __restrict__ tm,
                                              const float* __restrict__ tK,
                                              const float* __restrict__ tV) {
    int blk = blockIdx.x;
    int b = blk >> 6, qt = blk & 63;
    int tid = threadIdx.x;
    __shared__ float Qs[4][H_];
    __shared__ float S[16][L_];
    __shared__ int ts[4][L_];
    __shared__ int qs_s[4];

    if (tid < 4) {
        int j = tid;
        qs_s[j] = (j == 0) ? qt : (j == 1) ? (127 - qt) : (j == 2) ? (128 + qt) : (255 - qt);
    }
    __syncthreads();
    for (int i = tid; i < 4 * H_; i += 512) {
        int qi = i >> 8, c = i & 255;
        Qs[qi][c] = g_Q[(((b << 8) | qs_s[qi]) << 8) + c];
        ts[qi][c] = tm[(long)(((b << 8) | qs_s[qi])) * L_ + c];
    }
    for (int i = tid; i < 16 * L_; i += 512)
        S[i >> 8][i & 255] = BIGNEG;
    __syncthreads();

    int w = tid >> 5, lane = tid & 31;
    int qi = w >> 2, h = w & 3;
    int q = qs_s[qi];
    int bq = (b << 8) | q;
    int hd = h * D_;
    float q0r = Qs[qi][hd + lane], q1r = Qs[qi][hd + lane + 32];
    if (!g_mask[bq]) {
        for (int k = 0; k <= q; k++) {
            int t = ts[qi][k];
            const float* Kr = g_K + (((b << 8) | k) << 8) + hd;
            const float* tr = tK + (t << 8) + hd;
            float s = q0r * (Kr[lane] + tr[lane]);
            int d2 = lane + 32;
            s += q1r * (Kr[d2] + tr[d2]);
            #pragma unroll
            for (int o = 16; o; o >>= 1) s += __shfl_xor_sync(~0u, s, o);
            if (lane == 0) S[w][k] = s * 0.125f;
        }
    }
    __syncwarp();
    float e[8];
    float mx = BIGNEG;
    #pragma unroll
    for (int j = 0; j < 8; j++) { e[j] = S[w][lane + 32 * j]; mx = fmaxf(mx, e[j]); }
    #pragma unroll
    for (int o = 16; o; o >>= 1) mx = fmaxf(mx, __shfl_xor_sync(~0u, mx, o));
    float sum = 0.f;
    #pragma unroll
    for (int j = 0; j < 8; j++) { e[j] = __expf(e[j] - mx); sum += e[j]; }
    #pragma unroll
    for (int o = 16; o; o >>= 1) sum += __shfl_xor_sync(~0u, sum, o);
    float inv = 1.f / sum;
    #pragma unroll
    for (int j = 0; j < 8; j++) S[w][lane + 32 * j] = e[j] * inv;
    __syncthreads();

    int qi2 = tid >> 7, dp = (tid & 127) * 2;
    int h2 = dp >> 6;
    int q2 = qs_s[qi2];
    int bq2 = (b << 8) | q2;
    int kmax = g_mask[bq2] ? (L_ - 1) : q2;
    const float* Sp = S[qi2 * 4 + h2];
    float a0 = 0.f, a1 = 0.f;
    for (int k = 0; k <= kmax; k++) {
        float p = Sp[k];
        float2 v = *(const float2*)(g_V + (((b << 8) | k) << 8) + dp);
        float2 tv = *(const float2*)(tV + (ts[qi2][k] << 8) + dp);
        a0 += p * (v.x + tv.x);
        a1 += p * (v.y + tv.y);
    }
    g_att[(bq2 << 8) + dp] = a0;
    g_att[(bq2 << 8) + dp + 1] = a1;
}

extern "C" void kernel_launch(void* const* d_in, const int* in_sizes, int n_in,
                              void* d_out, int out_size) {
    const void*  mraw = d_in[0];
    const float* seq  = (const float*)d_in[1];
    const int*   tm   = (const int*)d_in[3];
    int base = (n_in >= 25 && in_sizes[4] == 1) ? 5 : 4;
    const float* Wq   = (const float*)d_in[base + 0];  const float* bq  = (const float*)d_in[base + 1];
    const float* Wk   = (const float*)d_in[base + 2];  const float* bk  = (const float*)d_in[base + 3];
    const float* Wv   = (const float*)d_in[base + 4];  const float* bv  = (const float*)d_in[base + 5];
    const float* ln1g = (const float*)d_in[base + 6];  const float* ln1b = (const float*)d_in[base + 7];
    const float* ln2g = (const float*)d_in[base + 8];  const float* ln2b = (const float*)d_in[base + 9];
    const float* W1   = (const float*)d_in[base + 10]; const float* b1  = (const float*)d_in[base + 11];
    const float* W2   = (const float*)d_in[base + 12]; const float* b2  = (const float*)d_in[base + 13];
    const float* posK = (const float*)d_in[base + 14]; const float* posV = (const float*)d_in[base + 15];
    const float* tK   = (const float*)d_in[base + 16]; const float* tV  = (const float*)d_in[base + 17];
    const float* lnfg = (const float*)d_in[base + 18]; const float* lnfb = (const float*)d_in[base + 19];
    float* out = (float*)d_out;

    float *px, *pq, *pQ, *pK, *pV, *patt, *pxa, *ph;
    cudaGetSymbolAddress((void**)&px,  g_x);
    cudaGetSymbolAddress((void**)&pq,  g_q);
    cudaGetSymbolAddress((void**)&pQ,  g_Q);
    cudaGetSymbolAddress((void**)&pK,  g_K);
    cudaGetSymbolAddress((void**)&pV,  g_V);
    cudaGetSymbolAddress((void**)&patt, g_att);
    cudaGetSymbolAddress((void**)&pxa, g_xa);
    cudaGetSymbolAddress((void**)&ph,  g_h);

    k_mask_convert<<<1, 256>>>(mraw);
    k_maskmul<<<PLANE / 256, 256>>>(seq);
    for (int i = 0; i < NBLK; i++) {
        const float* wq = Wq + (long)i * H_ * H_;
        const float* wk = Wk + (long)i * H_ * H_;
        const float* wv = Wv + (long)i * H_ * H_;
        const float* w1 = W1 + (long)i * H_ * H_;
        const float* w2 = W2 + (long)i * H_ * H_;

        k_ln<<<ROWS, 256>>>(px, nullptr, ln1g + i * H_, ln1b + i * H_, pq);

        TJobs jq;
        jq.j[0] = {pq, wq, bq + i * H_, nullptr, pQ, 0};
        jq.j[1] = {px, wk, bk + i * H_, posK,    pK, 1};
        jq.j[2] = {px, wv, bv + i * H_, posV,    pV, 2};
        k_gemm_tc<<<dim3(4, 32, 3), 256>>>(jq);

        k_attn<<<512, 512>>>(tm, tK, tV);

        k_ln<<<ROWS, 256>>>(pq, patt, ln2g + i * H_, ln2b + i * H_, pxa);

        TJobs j1;
        j1.j[0] = {pxa, w1, b1 + i * H_, nullptr, ph, 3};
        j1.j[1] = j1.j[0]; j1.j[2] = j1.j[0];
        k_gemm_tc<<<dim3(4, 32, 1), 256>>>(j1);

        TJobs j2;
        j2.j[0] = {ph, w2, b2 + i * H_, pxa, px, 4};
        j2.j[1] = j2.j[0]; j2.j[2] = j2.j[0];
        k_gemm_tc<<<dim3(4, 32, 1), 256>>>(j2);
    }
    k_ln<<<ROWS, 256>>>(px, nullptr, lnfg, lnfb, out);
}